// round 3
// baseline (speedup 1.0000x reference)
#include <cuda_runtime.h>

#define BATCH 32
#define HW    16384          // 128*128
#define NPIX  (BATCH * HW)   // 524288
#define NMIXK 10

__device__ double g_acc;

__global__ void zero_kernel() { g_acc = 0.0; }

__global__ void finish_kernel(float* out) { out[0] = (float)g_acc; }

// accurate tanh: 2 MUFU (EX2 + RCP), rel err ~1e-6
__device__ __forceinline__ float tanh_acc(float v) {
    float av = fabsf(v);
    float t  = __expf(-2.0f * av);                       // (0,1]
    float r  = (1.0f - t) * __fdividef(1.0f, 1.0f + t);
    return copysignf(r, v);
}

// per-(channel, mixture) log-prob contribution
__device__ __forceinline__ float chlp(float x, float mu, float lsr) {
    float ls   = fmaxf(lsr, -7.0f);
    float inv  = __expf(-ls);                 // MUFU 1
    float cent = x - mu;
    float mid  = inv * cent;
    float d    = inv * (1.0f / 255.0f);       // half-width, > 0
    float am   = fabsf(mid);

    // sinh(d), cosh(d): FMA polynomial for d <= 1 (covers ls > -5.54; other case ~1e-8 prob)
    float sh, ch;
    if (d <= 1.0f) {
        float d2 = d * d;
        sh = d * fmaf(d2, fmaf(d2, fmaf(d2, fmaf(d2, 2.7557319e-6f, 1.9841270e-4f),
                                        8.3333333e-3f), 0.16666667f), 1.0f);
        ch = fmaf(d2, fmaf(d2, fmaf(d2, fmaf(d2, 2.4801587e-5f, 1.3888889e-3f),
                                    4.1666667e-2f), 0.5f), 1.0f);
    } else {
        float ed  = __expf(d);
        float edi = __expf(-d);
        sh = 0.5f * (ed - edi);
        ch = 0.5f * (ed + edi);
    }

    // cdf_delta = sigmoid(mid+d) - sigmoid(mid-d), symmetric in mid, cancellation-free:
    //   delta = 2 g sinh(d) / (1 + 2 g cosh(d) + g^2),  g = exp(-|mid|) <= 1
    float g     = __expf(-am);                           // MUFU 2
    float denom = fmaf(2.0f * ch, g, fmaf(g, g, 1.0f));  // in [1, ~76]
    float rden  = __fdividef(1.0f, denom);               // MUFU 3
    float delta = 2.0f * g * sh * rden;

    // single-LG2 select:
    //  delta > 1e-5 : log(delta)
    //  else         : log_pdf_mid - log(127.5) = -ls - |mid| - 2*softplus(-|mid|) - log(127.5)
    //                 with -2*softplus(-|mid|) ~= log(rden)   (error <= 1e-5*tanh(d/2))
    float arg, lin;
    if (delta > 1e-5f) { arg = delta; lin = 0.0f; }
    else               { arg = rden;  lin = -ls - am - 4.8481164f; }
    float inner = __logf(arg) + lin;                     // MUFU 4

    // rare edge cases (x is a pixel-level constant -> uniform across the mixture loop)
    if (x < -0.999f) {
        float pz = mid + d;                                        // plus_in
        inner = fminf(pz, 0.0f) - __logf(1.0f + __expf(-fabsf(pz)));   // log sigmoid(plus_in)
    } else if (x > 0.999f) {
        float q = mid - d;                                         // min_in
        inner = -fmaxf(q, 0.0f) - __logf(1.0f + __expf(-fabsf(q)));    // -softplus(min_in)
    }
    return inner;
}

__global__ void __launch_bounds__(256) pixlp_kernel(
    const float* __restrict__ samples, const float* __restrict__ params)
{
    int p = blockIdx.x * blockDim.x + threadIdx.x;
    float val = 0.0f;
    if (p < NPIX) {
        int b  = p >> 14;
        int hw = p & (HW - 1);
        const float* sp = samples + (size_t)b * 3   * HW + hw;
        const float* pp = params  + (size_t)b * 100 * HW + hw;

        float x0 = fmaf(2.0f, __ldg(sp),          -1.0f);
        float x1 = fmaf(2.0f, __ldg(sp + HW),     -1.0f);
        float x2 = fmaf(2.0f, __ldg(sp + 2 * HW), -1.0f);

        float lg[NMIXK];
        #pragma unroll
        for (int i = 0; i < NMIXK; i++) lg[i] = __ldg(pp + i * HW);

        float mx = lg[0];
        #pragma unroll
        for (int i = 1; i < NMIXK; i++) mx = fmaxf(mx, lg[i]);
        float se = 0.0f;
        #pragma unroll
        for (int i = 0; i < NMIXK; i++) se += __expf(lg[i] - mx);
        float lse_logit = mx + __logf(se);

        float lp[NMIXK];
        #pragma unroll
        for (int m = 0; m < NMIXK; m++) {
            float mu1 = __ldg(pp + (10 + m) * HW);
            float ls1 = __ldg(pp + (20 + m) * HW);
            float c0r = __ldg(pp + (30 + m) * HW);
            float mu2 = __ldg(pp + (40 + m) * HW);
            float ls2 = __ldg(pp + (50 + m) * HW);
            float c1r = __ldg(pp + (60 + m) * HW);
            float mu3 = __ldg(pp + (70 + m) * HW);
            float ls3 = __ldg(pp + (80 + m) * HW);
            float c2r = __ldg(pp + (90 + m) * HW);

            float c0 = tanh_acc(c0r);
            float c1 = tanh_acc(c1r);
            float c2 = tanh_acc(c2r);

            float m2 = fmaf(c0, x0, mu2);
            float m3 = fmaf(c2, x1, fmaf(c1, x0, mu3));

            lp[m] = lg[m] + chlp(x0, mu1, ls1)
                          + chlp(x1, m2,  ls2)
                          + chlp(x2, m3,  ls3);
        }

        float mx2 = lp[0];
        #pragma unroll
        for (int i = 1; i < NMIXK; i++) mx2 = fmaxf(mx2, lp[i]);
        float s2 = 0.0f;
        #pragma unroll
        for (int i = 0; i < NMIXK; i++) s2 += __expf(lp[i] - mx2);

        val = mx2 + __logf(s2) - lse_logit;
    }

    // block reduction (fp32 within block, double across blocks)
    __shared__ float red[256];
    int t = threadIdx.x;
    red[t] = val;
    __syncthreads();
    #pragma unroll
    for (int off = 128; off > 0; off >>= 1) {
        if (t < off) red[t] += red[t + off];
        __syncthreads();
    }
    if (t == 0) atomicAdd(&g_acc, (double)red[0]);
}

extern "C" void kernel_launch(void* const* d_in, const int* in_sizes, int n_in,
                              void* d_out, int out_size)
{
    const float* samples;
    const float* params;
    if (in_sizes[0] == BATCH * 3 * HW) {
        samples = (const float*)d_in[0];
        params  = (const float*)d_in[1];
    } else {
        samples = (const float*)d_in[1];
        params  = (const float*)d_in[0];
    }
    zero_kernel<<<1, 1>>>();
    pixlp_kernel<<<NPIX / 256, 256>>>(samples, params);
    finish_kernel<<<1, 1>>>((float*)d_out);
}